// round 13
// baseline (speedup 1.0000x reference)
#include <cuda_runtime.h>
#include <cuda_fp16.h>
#include <cstdint>

#define NR 16384
#define NT 128                    // 128-row strips
#define TOT (NT * (NT + 1) / 2)   // 8256 triangle tiles
// exp(sim/T) = exp2(sim * 1/(T*ln2)), T=0.5 -> scale rows by sqrt(2.885390...)
#define SQRT_SCALE 1.6986436029926783f
#define E2C 7.389056098930650f    // exp(1/T) = e^2, exact diagonal term

#define ROWB 80                   // padded smem row stride (bytes)
#define TILE_B (128 * ROWB)       // 10240 B per tile buffer

__device__ unsigned short g_Q[NR * 32];   // e4m3 rows (64 fp8 = 32 ushort)
__device__ __half2 g_Y[NR * 32];          // f16 rows (numerator path)
__device__ float   g_RS[NR];              // row sums of exp2(arg)
__device__ float   g_sum;                 // global ratio accumulator
__device__ unsigned g_cnt;                // completion ticket

// ---------------------------------------------------------------------------
// Kernel 1: L2 normalize + scale; emit f16 (numerator) and e4m3 (GEMM) copies.
// ---------------------------------------------------------------------------
__global__ void k_normalize(const float* __restrict__ x) {
    int w    = (blockIdx.x * blockDim.x + threadIdx.x) >> 5;   // row
    int lane = threadIdx.x & 31;
    float2 v = ((const float2*)x)[w * 32 + lane];
    float ss = v.x * v.x + v.y * v.y;
#pragma unroll
    for (int o = 16; o > 0; o >>= 1) ss += __shfl_xor_sync(0xffffffffu, ss, o);
    float s = SQRT_SCALE * rsqrtf(fmaxf(ss, 1e-16f));
    float e0 = v.x * s, e1 = v.y * s;
    g_Y[w * 32 + lane] = __floats2half2_rn(e0, e1);
    unsigned short q;
    asm("cvt.rn.satfinite.e4m3x2.f32 %0, %1, %2;" : "=h"(q) : "f"(e1), "f"(e0));
    g_Q[w * 32 + lane] = q;
    if (lane == 0) g_RS[w] = 0.f;
}

// ---------------------------------------------------------------------------
// Kernel 2: triangular fused exp2(Q Q^T) -> row sums (rows + cols per tile).
// FP8 e4m3 m16n8k32 mma, f16 accumulators, ex2.approx.f16x2 off D.
// 296 persistent CTAs (2/SM); software-pipelined fragment chains.
// Measured at the legacy-tensor throughput floor — DO NOT TOUCH.
// ---------------------------------------------------------------------------
__device__ __forceinline__ void cp16(void* dst, const void* src) {
    unsigned d = (unsigned)__cvta_generic_to_shared(dst);
    asm volatile("cp.async.ca.shared.global [%0], [%1], 16;\n" ::"r"(d), "l"(src));
}

// one 128-row x 64B fp8 tile into smem with ROWB padding
__device__ __forceinline__ void prefetch_tile(uint8_t* buf, int rowbase, int tid) {
    const char* src = (const char*)g_Q;
#pragma unroll
    for (int it = 0; it < 2; it++) {
        int u = tid + it * 256;               // 0..511 16B chunks
        int r = u >> 2, cdx = u & 3;
        cp16(buf + r * ROWB + cdx * 16,
             src + (size_t)(rowbase + r) * 64 + cdx * 16);
    }
}

#define MMA_PAIR(dst0, dst1, A, B)                                          \
    asm("mma.sync.aligned.m16n8k32.row.col.f16.e4m3.e4m3.f16 "              \
        "{%0,%1},{%2,%3,%4,%5},{%6,%7},{%0,%1};\n"                          \
        : "+r"(dst0), "+r"(dst1)                                            \
        : "r"((A)[0][0]), "r"((A)[0][1]), "r"((A)[0][2]), "r"((A)[0][3]),   \
          "r"((B)[0][0]), "r"((B)[0][1]));                                  \
    asm("mma.sync.aligned.m16n8k32.row.col.f16.e4m3.e4m3.f16 "              \
        "{%0,%1},{%2,%3,%4,%5},{%6,%7},{%0,%1};\n"                          \
        : "+r"(dst0), "+r"(dst1)                                            \
        : "r"((A)[1][0]), "r"((A)[1][1]), "r"((A)[1][2]), "r"((A)[1][3]),   \
          "r"((B)[1][0]), "r"((B)[1][1]));

#define CONSUME(src0, src1, pmf, ps)                                        \
    {                                                                       \
        unsigned e0, e1;                                                    \
        asm("ex2.approx.f16x2 %0, %1;" : "=r"(e0) : "r"(src0));             \
        asm("ex2.approx.f16x2 %0, %1;" : "=r"(e1) : "r"(src1));             \
        asm("add.f16x2 %0, %0, %1;" : "+r"(racc0[pmf]) : "r"(e0));          \
        asm("add.f16x2 %0, %0, %1;" : "+r"(racc1[pmf]) : "r"(e1));          \
        asm("add.f16x2 %0, %0, %1;" : "+r"(cacc[ps]) : "r"(e0));            \
        asm("add.f16x2 %0, %0, %1;" : "+r"(cacc[ps]) : "r"(e1));            \
    }

__global__ void __launch_bounds__(256, 2) k_main() {
    __shared__ __align__(16) uint8_t bufA[2][TILE_B];
    __shared__ __align__(16) uint8_t bufB[2][TILE_B];
    __shared__ float red[2][128][4];
    __shared__ float cred[2][128][2];

    int tid  = threadIdx.x;
    int warp = tid >> 5, lane = tid & 31;
    int r = warp >> 2, c = warp & 3;          // row-group / column-group
    int rbase = r * 64;
    int g   = lane >> 2;                      // 0..7 (row within m16 block)
    int tig = lane & 3;                       // 0..3

    int start = (int)(((long long)TOT * blockIdx.x) / gridDim.x);
    int end   = (int)(((long long)TOT * (blockIdx.x + 1)) / gridDim.x);

    // locate starting (I, J) in row-major upper triangle
    int I = 0, acc = 0;
    while (acc + (NT - I) <= start) { acc += NT - I; I++; }
    int J = I + (start - acc);

    prefetch_tile(bufA[0], I * 128, tid);
    prefetch_tile(bufB[0], J * 128, tid);
    asm volatile("cp.async.commit_group;\n");

    for (int p = start; p < end; p++) {
        int buf = (p - start) & 1;
        int nI = I, nJ = J + 1;
        if (nJ == NT) { nI++; nJ = nI; }
        if (p + 1 < end) {
            prefetch_tile(bufA[buf ^ 1], nI * 128, tid);
            prefetch_tile(bufB[buf ^ 1], nJ * 128, tid);
            asm volatile("cp.async.commit_group;\n");
            asm volatile("cp.async.wait_group 1;\n");
        } else {
            asm volatile("cp.async.wait_group 0;\n");
        }
        __syncthreads();    // tile p data ready; prev iter's red/cred readers done

        const uint8_t* smA = bufA[buf];
        const uint8_t* smB = bufB[buf];

        // A fragments: m16n8k32 e4m3. a0:(g,k0..3) a1:(g+8) a2:(g,k16) a3:(g+8,k16)
        unsigned a[4][2][4];
#pragma unroll
        for (int mf = 0; mf < 4; mf++) {
#pragma unroll
            for (int kc = 0; kc < 2; kc++) {
                const uint8_t* ap = smA + (rbase + mf * 16 + g) * ROWB + kc * 32 + tig * 4;
                a[mf][kc][0] = *(const unsigned*)(ap);
                a[mf][kc][1] = *(const unsigned*)(ap + 8 * ROWB);
                a[mf][kc][2] = *(const unsigned*)(ap + 16);
                a[mf][kc][3] = *(const unsigned*)(ap + 8 * ROWB + 16);
            }
        }
        // B fragments for all 4 column sub-tiles.
        unsigned b[4][2][2];
#pragma unroll
        for (int s = 0; s < 4; s++) {
            const uint8_t* bp = smB + ((c + s * 4) * 8 + g) * ROWB + tig * 4;
#pragma unroll
            for (int kc = 0; kc < 2; kc++) {
                b[s][kc][0] = *(const unsigned*)(bp + kc * 32);
                b[s][kc][1] = *(const unsigned*)(bp + kc * 32 + 16);
            }
        }

        unsigned racc0[4] = {0, 0, 0, 0};   // f16x2 row accum (row g)
        unsigned racc1[4] = {0, 0, 0, 0};   // (row g+8)
        unsigned cacc[4]  = {0, 0, 0, 0};   // f16x2 col accum per s

        // Software-pipelined chains: i = s*4 + mf.
        unsigned d[2][2];
        d[0][0] = 0; d[0][1] = 0;
        MMA_PAIR(d[0][0], d[0][1], a[0], b[0]);
#pragma unroll
        for (int i = 1; i < 16; i++) {
            int s = i >> 2, mf = i & 3;
            int pi = i - 1, ps = pi >> 2, pmf = pi & 3;
            d[i & 1][0] = 0; d[i & 1][1] = 0;
            MMA_PAIR(d[i & 1][0], d[i & 1][1], a[mf], b[s]);
            CONSUME(d[pi & 1][0], d[pi & 1][1], pmf, ps);
        }
        CONSUME(d[1][0], d[1][1], 3, 3);

        // Row sums: lo+hi then reduce over tig (4 lanes per row).
#pragma unroll
        for (int mf = 0; mf < 4; mf++) {
            float2 f0 = __half22float2(*reinterpret_cast<__half2*>(&racc0[mf]));
            float2 f1 = __half22float2(*reinterpret_cast<__half2*>(&racc1[mf]));
            float v0 = f0.x + f0.y;
            float v1 = f1.x + f1.y;
            v0 += __shfl_xor_sync(0xffffffffu, v0, 1);
            v0 += __shfl_xor_sync(0xffffffffu, v0, 2);
            v1 += __shfl_xor_sync(0xffffffffu, v1, 1);
            v1 += __shfl_xor_sync(0xffffffffu, v1, 2);
            if (tig == 0) {
                red[buf][rbase + mf * 16 + g][c]     = v0;
                red[buf][rbase + mf * 16 + 8 + g][c] = v1;
            }
        }
        // Col sums: reduce over g (stride-4 lanes) per (s, half).
#pragma unroll
        for (int s = 0; s < 4; s++) {
            float2 cf = __half22float2(*reinterpret_cast<__half2*>(&cacc[s]));
#pragma unroll
            for (int h = 0; h < 2; h++) {
                float v = h ? cf.y : cf.x;
                v += __shfl_xor_sync(0xffffffffu, v, 4);
                v += __shfl_xor_sync(0xffffffffu, v, 8);
                v += __shfl_xor_sync(0xffffffffu, v, 16);
                if (g == 0)
                    cred[buf][(c + s * 4) * 8 + tig * 2 + h][r] = v;
            }
        }
        __syncthreads();    // red/cred[buf] complete

        if (tid < 128) {
            const float* rp = red[buf][tid];
            atomicAdd(&g_RS[I * 128 + tid], rp[0] + rp[1] + rp[2] + rp[3]);
            if (I != J) {
                const float* cp = cred[buf][tid];
                atomicAdd(&g_RS[J * 128 + tid], cp[0] + cp[1]);
            }
        }
        I = nI; J = nJ;
    }
}

// ---------------------------------------------------------------------------
// Kernel 3 (fused final+loss): numerator, ratio, block reduce, global
// accumulate; LAST block computes -log(mean) and resets the globals so the
// kernel is graph-replay safe.
// ---------------------------------------------------------------------------
__global__ void k_final(float* __restrict__ out) {
    __shared__ float redsm[8];
    int i = blockIdx.x * 256 + threadIdx.x;
    int j = i ^ 1;
    const __half2* yi = g_Y + i * 32;
    const __half2* yj = g_Y + j * 32;
    float dot = 0.f;
#pragma unroll
    for (int k = 0; k < 32; k++) {
        float2 av = __half22float2(yi[k]);
        float2 bv = __half22float2(yj[k]);
        dot += av.x * bv.x + av.y * bv.y;
    }
    float ratio = exp2f(dot) / (g_RS[i] - E2C);

    int lane = threadIdx.x & 31, w = threadIdx.x >> 5;
#pragma unroll
    for (int o = 16; o > 0; o >>= 1) ratio += __shfl_xor_sync(0xffffffffu, ratio, o);
    if (lane == 0) redsm[w] = ratio;
    __syncthreads();
    if (threadIdx.x == 0) {
        float v = redsm[0] + redsm[1] + redsm[2] + redsm[3] +
                  redsm[4] + redsm[5] + redsm[6] + redsm[7];
        atomicAdd(&g_sum, v);
        __threadfence();
        unsigned ticket = atomicAdd(&g_cnt, 1u);
        if (ticket == gridDim.x - 1) {          // last block: finalize + reset
            float total = *((volatile float*)&g_sum);
            out[0] = -logf(total * (1.0f / (float)NR));
            g_sum = 0.f;
            g_cnt = 0u;
        }
    }
}

// ---------------------------------------------------------------------------
extern "C" void kernel_launch(void* const* d_in, const int* in_sizes, int n_in,
                              void* d_out, int out_size) {
    const float* x = (const float*)d_in[0];
    k_normalize<<<NR / 8, 256>>>(x);     // 8 rows (warps) per block
    k_main<<<296, 256>>>();              // 2 CTAs per SM
    k_final<<<NR / 256, 256>>>((float*)d_out);
}

// round 15
// speedup vs baseline: 1.1246x; 1.1246x over previous
#include <cuda_runtime.h>
#include <cuda_fp16.h>
#include <cstdint>

#define NR 16384
#define NT 128                    // 128-row strips
#define TOT (NT * (NT + 1) / 2)   // 8256 triangle tiles
// exp(sim/T) = exp2(sim * 1/(T*ln2)), T=0.5 -> scale rows by sqrt(2.885390...)
#define SQRT_SCALE 1.6986436029926783f
#define E2C 7.389056098930650f    // exp(1/T) = e^2, exact diagonal term

#define ROWB 80                   // padded smem row stride (bytes)
#define TILE_B (128 * ROWB)       // 10240 B per tile buffer

__device__ unsigned short g_Q[NR * 32];   // e4m3 rows (64 fp8 = 32 ushort)
__device__ __half2 g_Y[NR * 32];          // f16 rows (numerator path)
__device__ float   g_RS[NR];              // row sums of exp2(arg)
__device__ float   g_sum;                 // global ratio accumulator
__device__ unsigned g_cnt;                // completion ticket

// ---------------------------------------------------------------------------
// Kernel 1: L2 normalize + scale. 4 rows per warp, 8 lanes per row, float4
// loads (MLP=2/lane), 3-step shfl reduce, vectorized f16/e4m3 stores.
// ---------------------------------------------------------------------------
__global__ void k_normalize(const float* __restrict__ x) {
    int warp = (blockIdx.x * blockDim.x + threadIdx.x) >> 5;
    int lane = threadIdx.x & 31;
    int sr  = lane >> 3;                   // sub-row 0..3
    int li  = lane & 7;                    // lane within row
    int row = warp * 4 + sr;

    const float4* xp = (const float4*)(x + (size_t)row * 64 + li * 8);
    float4 v0 = xp[0];
    float4 v1 = xp[1];
    float ss = v0.x * v0.x + v0.y * v0.y + v0.z * v0.z + v0.w * v0.w
             + v1.x * v1.x + v1.y * v1.y + v1.z * v1.z + v1.w * v1.w;
#pragma unroll
    for (int o = 1; o < 8; o <<= 1) ss += __shfl_xor_sync(0xffffffffu, ss, o);
    float s = SQRT_SCALE * rsqrtf(fmaxf(ss, 1e-16f));

    float f[8] = {v0.x * s, v0.y * s, v0.z * s, v0.w * s,
                  v1.x * s, v1.y * s, v1.z * s, v1.w * s};
    // f16 copy: 4 half2 = 16B vectorized store
    __half2 h0 = __floats2half2_rn(f[0], f[1]);
    __half2 h1 = __floats2half2_rn(f[2], f[3]);
    __half2 h2 = __floats2half2_rn(f[4], f[5]);
    __half2 h3 = __floats2half2_rn(f[6], f[7]);
    uint4 hv;
    hv.x = *(unsigned*)&h0; hv.y = *(unsigned*)&h1;
    hv.z = *(unsigned*)&h2; hv.w = *(unsigned*)&h3;
    *(uint4*)(g_Y + (size_t)row * 32 + li * 4) = hv;
    // e4m3 copy: 4 ushort = 8B vectorized store
    unsigned short q0, q1, q2, q3;
    asm("cvt.rn.satfinite.e4m3x2.f32 %0, %1, %2;" : "=h"(q0) : "f"(f[1]), "f"(f[0]));
    asm("cvt.rn.satfinite.e4m3x2.f32 %0, %1, %2;" : "=h"(q1) : "f"(f[3]), "f"(f[2]));
    asm("cvt.rn.satfinite.e4m3x2.f32 %0, %1, %2;" : "=h"(q2) : "f"(f[5]), "f"(f[4]));
    asm("cvt.rn.satfinite.e4m3x2.f32 %0, %1, %2;" : "=h"(q3) : "f"(f[7]), "f"(f[6]));
    ushort4 qv = make_ushort4(q0, q1, q2, q3);
    *(ushort4*)(g_Q + (size_t)row * 32 + li * 4) = qv;
    if (li == 0) g_RS[row] = 0.f;
}

// ---------------------------------------------------------------------------
// Kernel 2: triangular fused exp2(Q Q^T) -> row sums (rows + cols per tile).
// FP8 e4m3 m16n8k32 mma, f16 accumulators, ex2.approx.f16x2 off D.
// 296 persistent CTAs (2/SM); software-pipelined fragment chains.
// Measured at the legacy-tensor throughput floor — DO NOT TOUCH.
// ---------------------------------------------------------------------------
__device__ __forceinline__ void cp16(void* dst, const void* src) {
    unsigned d = (unsigned)__cvta_generic_to_shared(dst);
    asm volatile("cp.async.ca.shared.global [%0], [%1], 16;\n" ::"r"(d), "l"(src));
}

__device__ __forceinline__ void prefetch_tile(uint8_t* buf, int rowbase, int tid) {
    const char* src = (const char*)g_Q;
#pragma unroll
    for (int it = 0; it < 2; it++) {
        int u = tid + it * 256;               // 0..511 16B chunks
        int r = u >> 2, cdx = u & 3;
        cp16(buf + r * ROWB + cdx * 16,
             src + (size_t)(rowbase + r) * 64 + cdx * 16);
    }
}

#define MMA_PAIR(dst0, dst1, A, B)                                          \
    asm("mma.sync.aligned.m16n8k32.row.col.f16.e4m3.e4m3.f16 "              \
        "{%0,%1},{%2,%3,%4,%5},{%6,%7},{%0,%1};\n"                          \
        : "+r"(dst0), "+r"(dst1)                                            \
        : "r"((A)[0][0]), "r"((A)[0][1]), "r"((A)[0][2]), "r"((A)[0][3]),   \
          "r"((B)[0][0]), "r"((B)[0][1]));                                  \
    asm("mma.sync.aligned.m16n8k32.row.col.f16.e4m3.e4m3.f16 "              \
        "{%0,%1},{%2,%3,%4,%5},{%6,%7},{%0,%1};\n"                          \
        : "+r"(dst0), "+r"(dst1)                                            \
        : "r"((A)[1][0]), "r"((A)[1][1]), "r"((A)[1][2]), "r"((A)[1][3]),   \
          "r"((B)[1][0]), "r"((B)[1][1]));

#define CONSUME(src0, src1, pmf, ps)                                        \
    {                                                                       \
        unsigned e0, e1;                                                    \
        asm("ex2.approx.f16x2 %0, %1;" : "=r"(e0) : "r"(src0));             \
        asm("ex2.approx.f16x2 %0, %1;" : "=r"(e1) : "r"(src1));             \
        asm("add.f16x2 %0, %0, %1;" : "+r"(racc0[pmf]) : "r"(e0));          \
        asm("add.f16x2 %0, %0, %1;" : "+r"(racc1[pmf]) : "r"(e1));          \
        asm("add.f16x2 %0, %0, %1;" : "+r"(cacc[ps]) : "r"(e0));            \
        asm("add.f16x2 %0, %0, %1;" : "+r"(cacc[ps]) : "r"(e1));            \
    }

__global__ void __launch_bounds__(256, 2) k_main() {
    __shared__ __align__(16) uint8_t bufA[2][TILE_B];
    __shared__ __align__(16) uint8_t bufB[2][TILE_B];
    __shared__ float red[2][128][4];
    __shared__ float cred[2][128][2];

    int tid  = threadIdx.x;
    int warp = tid >> 5, lane = tid & 31;
    int r = warp >> 2, c = warp & 3;          // row-group / column-group
    int rbase = r * 64;
    int g   = lane >> 2;                      // 0..7 (row within m16 block)
    int tig = lane & 3;                       // 0..3

    int start = (int)(((long long)TOT * blockIdx.x) / gridDim.x);
    int end   = (int)(((long long)TOT * (blockIdx.x + 1)) / gridDim.x);

    int I = 0, acc = 0;
    while (acc + (NT - I) <= start) { acc += NT - I; I++; }
    int J = I + (start - acc);

    prefetch_tile(bufA[0], I * 128, tid);
    prefetch_tile(bufB[0], J * 128, tid);
    asm volatile("cp.async.commit_group;\n");

    for (int p = start; p < end; p++) {
        int buf = (p - start) & 1;
        int nI = I, nJ = J + 1;
        if (nJ == NT) { nI++; nJ = nI; }
        if (p + 1 < end) {
            prefetch_tile(bufA[buf ^ 1], nI * 128, tid);
            prefetch_tile(bufB[buf ^ 1], nJ * 128, tid);
            asm volatile("cp.async.commit_group;\n");
            asm volatile("cp.async.wait_group 1;\n");
        } else {
            asm volatile("cp.async.wait_group 0;\n");
        }
        __syncthreads();

        const uint8_t* smA = bufA[buf];
        const uint8_t* smB = bufB[buf];

        unsigned a[4][2][4];
#pragma unroll
        for (int mf = 0; mf < 4; mf++) {
#pragma unroll
            for (int kc = 0; kc < 2; kc++) {
                const uint8_t* ap = smA + (rbase + mf * 16 + g) * ROWB + kc * 32 + tig * 4;
                a[mf][kc][0] = *(const unsigned*)(ap);
                a[mf][kc][1] = *(const unsigned*)(ap + 8 * ROWB);
                a[mf][kc][2] = *(const unsigned*)(ap + 16);
                a[mf][kc][3] = *(const unsigned*)(ap + 8 * ROWB + 16);
            }
        }
        unsigned b[4][2][2];
#pragma unroll
        for (int s = 0; s < 4; s++) {
            const uint8_t* bp = smB + ((c + s * 4) * 8 + g) * ROWB + tig * 4;
#pragma unroll
            for (int kc = 0; kc < 2; kc++) {
                b[s][kc][0] = *(const unsigned*)(bp + kc * 32);
                b[s][kc][1] = *(const unsigned*)(bp + kc * 32 + 16);
            }
        }

        unsigned racc0[4] = {0, 0, 0, 0};
        unsigned racc1[4] = {0, 0, 0, 0};
        unsigned cacc[4]  = {0, 0, 0, 0};

        unsigned d[2][2];
        d[0][0] = 0; d[0][1] = 0;
        MMA_PAIR(d[0][0], d[0][1], a[0], b[0]);
#pragma unroll
        for (int i = 1; i < 16; i++) {
            int s = i >> 2, mf = i & 3;
            int pi = i - 1, ps = pi >> 2, pmf = pi & 3;
            d[i & 1][0] = 0; d[i & 1][1] = 0;
            MMA_PAIR(d[i & 1][0], d[i & 1][1], a[mf], b[s]);
            CONSUME(d[pi & 1][0], d[pi & 1][1], pmf, ps);
        }
        CONSUME(d[1][0], d[1][1], 3, 3);

#pragma unroll
        for (int mf = 0; mf < 4; mf++) {
            float2 f0 = __half22float2(*reinterpret_cast<__half2*>(&racc0[mf]));
            float2 f1 = __half22float2(*reinterpret_cast<__half2*>(&racc1[mf]));
            float v0 = f0.x + f0.y;
            float v1 = f1.x + f1.y;
            v0 += __shfl_xor_sync(0xffffffffu, v0, 1);
            v0 += __shfl_xor_sync(0xffffffffu, v0, 2);
            v1 += __shfl_xor_sync(0xffffffffu, v1, 1);
            v1 += __shfl_xor_sync(0xffffffffu, v1, 2);
            if (tig == 0) {
                red[buf][rbase + mf * 16 + g][c]     = v0;
                red[buf][rbase + mf * 16 + 8 + g][c] = v1;
            }
        }
#pragma unroll
        for (int s = 0; s < 4; s++) {
            float2 cf = __half22float2(*reinterpret_cast<__half2*>(&cacc[s]));
#pragma unroll
            for (int h = 0; h < 2; h++) {
                float v = h ? cf.y : cf.x;
                v += __shfl_xor_sync(0xffffffffu, v, 4);
                v += __shfl_xor_sync(0xffffffffu, v, 8);
                v += __shfl_xor_sync(0xffffffffu, v, 16);
                if (g == 0)
                    cred[buf][(c + s * 4) * 8 + tig * 2 + h][r] = v;
            }
        }
        __syncthreads();

        if (tid < 128) {
            const float* rp = red[buf][tid];
            atomicAdd(&g_RS[I * 128 + tid], rp[0] + rp[1] + rp[2] + rp[3]);
            if (I != J) {
                const float* cp = cred[buf][tid];
                atomicAdd(&g_RS[J * 128 + tid], cp[0] + cp[1]);
            }
        }
        I = nI; J = nJ;
    }
}

// ---------------------------------------------------------------------------
// Kernel 3 (fused final+loss): one thread per POSITIVE PAIR (rows 2p, 2p+1,
// contiguous 256B). dot computed once; ratio_i + ratio_j = num*(1/di + 1/dj).
// 128 CTAs x 64 threads; last block finalizes -log(mean) and resets globals.
// ---------------------------------------------------------------------------
__global__ void k_final(float* __restrict__ out) {
    __shared__ float redsm[2];
    int p = blockIdx.x * 64 + threadIdx.x;    // pair index, 0..8191
    const uint4* yp = (const uint4*)g_Y + (size_t)p * 16;  // 2 rows = 16 uint4

    float dot = 0.f;
#pragma unroll
    for (int k = 0; k < 8; k++) {
        uint4 ua = yp[k];
        uint4 ub = yp[8 + k];
        const __half2* ha = (const __half2*)&ua;
        const __half2* hb = (const __half2*)&ub;
#pragma unroll
        for (int q = 0; q < 4; q++) {
            float2 fa = __half22float2(ha[q]);
            float2 fb = __half22float2(hb[q]);
            dot += fa.x * fb.x + fa.y * fb.y;
        }
    }
    float num = exp2f(dot);                   // dot carries 1/(T ln2) scale
    float2 den = ((const float2*)g_RS)[p];
    float ratio = num / (den.x - E2C) + num / (den.y - E2C);

    int lane = threadIdx.x & 31, w = threadIdx.x >> 5;
#pragma unroll
    for (int o = 16; o > 0; o >>= 1) ratio += __shfl_xor_sync(0xffffffffu, ratio, o);
    if (lane == 0) redsm[w] = ratio;
    __syncthreads();
    if (threadIdx.x == 0) {
        atomicAdd(&g_sum, redsm[0] + redsm[1]);
        __threadfence();
        unsigned ticket = atomicAdd(&g_cnt, 1u);
        if (ticket == gridDim.x - 1) {        // last block: finalize + reset
            float total = *((volatile float*)&g_sum);
            out[0] = -logf(total * (1.0f / (float)NR));
            g_sum = 0.f;
            g_cnt = 0u;
        }
    }
}

// ---------------------------------------------------------------------------
extern "C" void kernel_launch(void* const* d_in, const int* in_sizes, int n_in,
                              void* d_out, int out_size) {
    const float* x = (const float*)d_in[0];
    k_normalize<<<NR / 32, 256>>>(x);    // 4 rows/warp, 8 warps/block
    k_main<<<296, 256>>>();              // 2 CTAs per SM
    k_final<<<NR / 128, 64>>>((float*)d_out);
}